// round 15
// baseline (speedup 1.0000x reference)
#include <cuda_runtime.h>
#include <cuda_fp16.h>
#include <cstdint>

// Problem constants
#define B_  8
#define T_  256
#define U_  64
#define D_  512
#define V_  1024

// Tiling: CTA 128x256, warp grid 2x4, warp tile 64x64
#define BM 128
#define BN 256
#define KC 32             // k-chunk (2 x K=16 MMA steps)
#define NCHUNK 16         // D_/KC
#define ST 40             // smem row stride in halves (32 + 8 pad), conflict-free
#define A_TILE_H (BM * ST)   // 5120 halves per stage
#define B_TILE_H (BN * ST)   // 10240 halves per stage
#define SMEM_BYTES ((2 * A_TILE_H + 2 * B_TILE_H) * 2)   // 61440

// fp16 scratch (allocation-free per harness rules)
__device__ __align__(16) __half g_W16[V_ * D_];
__device__ __align__(16) __half g_S16[B_ * T_ * D_];
__device__ __align__(16) __half g_T16[B_ * U_ * D_];

__global__ void convert_f2h_kernel(const float* __restrict__ in, __half* __restrict__ out) {
    int i = (blockIdx.x * blockDim.x + threadIdx.x) * 4;
    float4 w = *(const float4*)(in + i);
    union { __half2 h[2]; uint2 u; } pack;
    pack.h[0] = __floats2half2_rn(w.x, w.y);
    pack.h[1] = __floats2half2_rn(w.z, w.w);
    *(uint2*)(out + i) = pack.u;
}

__global__ void write_lengths_kernel(const int* __restrict__ slen,
                                     const int* __restrict__ tlen,
                                     float* __restrict__ out_tail) {
    int i = threadIdx.x;
    if (i < B_)          out_tail[i] = (float)slen[i];
    else if (i < 2 * B_) out_tail[i] = (float)tlen[i - B_];
}

__device__ __forceinline__ void cp_async16(void* smem_dst, const void* gsrc) {
    uint32_t d = (uint32_t)__cvta_generic_to_shared(smem_dst);
    asm volatile("cp.async.ca.shared.global [%0], [%1], 16;" :: "r"(d), "l"(gsrc));
}
#define CP_COMMIT() asm volatile("cp.async.commit_group;" ::: "memory")
#define CP_WAIT0()  asm volatile("cp.async.wait_group 0;" ::: "memory")

// cp.async chunk c of B: 256 rows x 64B = 1024 x16B groups; 4 ops/thread.
__device__ __forceinline__ void cp_B(__half* Bs_s, int v0, int c, int tid) {
    #pragma unroll
    for (int it = 0; it < 4; ++it) {
        int G = tid + it * 256;       // 0..1023
        int n = G >> 2;               // B row 0..255
        int g = G & 3;                // 16B group within row
        cp_async16(Bs_s + n * ST + g * 8,
                   g_W16 + (size_t)(v0 + n) * D_ + c * KC + g * 8);
    }
}

// Load chunk c's fp16 A operands (2 threads per row, 16 halves each stream).
__device__ __forceinline__ void load_A(int m_base, int c, int tid,
                                       uint4 rs[2], uint4 rt[2]) {
    int r = tid >> 1, h = tid & 1;
    int b = m_base >> 14;
    int t_idx = ((m_base & 16383) >> 6) + (r >> 6);
    const uint4* sp = (const uint4*)(g_S16 + (size_t)(b * T_ + t_idx) * D_ + c * KC + h * 16);
    const uint4* tp = (const uint4*)(g_T16 + (size_t)(b * U_ + (r & 63)) * D_ + c * KC + h * 16);
    rs[0] = sp[0]; rs[1] = sp[1];
    rt[0] = tp[0]; rt[1] = tp[1];
}

// relu(src+tgt) in half2, store 16 halves.
__device__ __forceinline__ void store_A(__half* __restrict__ As_s, int tid,
                                        const uint4 rs[2], const uint4 rt[2]) {
    int r = tid >> 1, h = tid & 1;
    __half* dst = As_s + r * ST + h * 16;
    const __half2 z = __float2half2_rn(0.f);
    #pragma unroll
    for (int j = 0; j < 2; ++j) {
        union { uint4 v; __half2 h2[4]; } a, b, o;
        a.v = rs[j]; b.v = rt[j];
        #pragma unroll
        for (int q = 0; q < 4; ++q) o.h2[q] = __hmax2(__hadd2(a.h2[q], b.h2[q]), z);
        *(uint4*)(dst + j * 8) = o.v;
    }
}

__device__ __forceinline__ void compute_chunk(const __half* __restrict__ As_s,
                                              const __half* __restrict__ Bs_s,
                                              int wm, int wn, int lane,
                                              float acc[4][8][4]) {
    #pragma unroll
    for (int kk = 0; kk < KC; kk += 16) {
        uint32_t afr[4][4], bfr[4][4];
        #pragma unroll
        for (int mt = 0; mt < 4; ++mt) {
            int row = wm * 64 + mt * 16 + (lane & 15);
            int col = kk + ((lane >> 4) << 3);
            uint32_t addr = (uint32_t)__cvta_generic_to_shared(As_s + row * ST + col);
            asm volatile("ldmatrix.sync.aligned.m8n8.x4.shared.b16 {%0,%1,%2,%3}, [%4];"
                         : "=r"(afr[mt][0]), "=r"(afr[mt][1]), "=r"(afr[mt][2]), "=r"(afr[mt][3])
                         : "r"(addr));
        }
        #pragma unroll
        for (int nb = 0; nb < 4; ++nb) {
            int row = wn * 64 + nb * 16 + (lane & 15);
            int col = kk + ((lane >> 4) << 3);
            uint32_t addr = (uint32_t)__cvta_generic_to_shared(Bs_s + row * ST + col);
            asm volatile("ldmatrix.sync.aligned.m8n8.x4.shared.b16 {%0,%1,%2,%3}, [%4];"
                         : "=r"(bfr[nb][0]), "=r"(bfr[nb][1]), "=r"(bfr[nb][2]), "=r"(bfr[nb][3])
                         : "r"(addr));
        }
        #pragma unroll
        for (int mt = 0; mt < 4; ++mt)
            #pragma unroll
            for (int nt = 0; nt < 8; ++nt) {
                // n8 tile nt: regs {bfr[nt>>1][nt&1], bfr[nt>>1][(nt&1)+2]}
                asm volatile(
                    "mma.sync.aligned.m16n8k16.row.col.f32.f16.f16.f32 "
                    "{%0,%1,%2,%3}, {%4,%5,%6,%7}, {%8,%9}, {%0,%1,%2,%3};"
                    : "+f"(acc[mt][nt][0]), "+f"(acc[mt][nt][1]),
                      "+f"(acc[mt][nt][2]), "+f"(acc[mt][nt][3])
                    : "r"(afr[mt][0]), "r"(afr[mt][1]), "r"(afr[mt][2]), "r"(afr[mt][3]),
                      "r"(bfr[nt >> 1][nt & 1]), "r"(bfr[nt >> 1][(nt & 1) + 2]));
            }
    }
}

__global__ void __launch_bounds__(256, 1)
joiner_gemm_kernel(const float* __restrict__ bias, float* __restrict__ out)
{
    extern __shared__ __half sm[];
    __half* As = sm;                       // 2 stages x 5120
    __half* Bs = sm + 2 * A_TILE_H;        // 2 stages x 10240

    const int tid  = threadIdx.x;
    const int lane = tid & 31;
    const int warp = tid >> 5;
    const int wm = warp >> 2;     // 0..1
    const int wn = warp & 3;      // 0..3
    const int v0 = blockIdx.x * BN;
    const int m_base = blockIdx.y * BM;

    float acc[4][8][4];
    #pragma unroll
    for (int i = 0; i < 4; ++i)
        #pragma unroll
        for (int j = 0; j < 8; ++j)
            #pragma unroll
            for (int k = 0; k < 4; ++k) acc[i][j][k] = 0.f;

    // ---- prologue: chunk 0 ----
    cp_B(Bs, v0, 0, tid);
    CP_COMMIT();
    {
        uint4 rs[2], rt[2];
        load_A(m_base, 0, tid, rs, rt);
        store_A(As, tid, rs, rt);
    }
    CP_WAIT0();
    __syncthreads();

    // ---- main pipeline: one sync per chunk ----
    for (int c = 0; c < NCHUNK; ++c) {
        const int s = c & 1;
        uint4 rs[2], rt[2];
        if (c < NCHUNK - 1) {
            cp_B(Bs + (s ^ 1) * B_TILE_H, v0, c + 1, tid);
            CP_COMMIT();
            load_A(m_base, c + 1, tid, rs, rt);
        }
        compute_chunk(As + s * A_TILE_H, Bs + s * B_TILE_H, wm, wn, lane, acc);
        if (c < NCHUNK - 1) store_A(As + (s ^ 1) * A_TILE_H, tid, rs, rt);
        CP_WAIT0();
        __syncthreads();
    }

    // ---- epilogue: bias + fp32 store ----
    #pragma unroll
    for (int nt = 0; nt < 8; ++nt) {
        int col = v0 + wn * 64 + nt * 8 + ((lane & 3) << 1);
        float2 bv = *(const float2*)(bias + col);
        #pragma unroll
        for (int mt = 0; mt < 4; ++mt) {
            int row = m_base + wm * 64 + mt * 16 + (lane >> 2);
            float2 r0 = make_float2(acc[mt][nt][0] + bv.x, acc[mt][nt][1] + bv.y);
            float2 r1 = make_float2(acc[mt][nt][2] + bv.x, acc[mt][nt][3] + bv.y);
            *(float2*)(out + (size_t)row * V_ + col)       = r0;
            *(float2*)(out + (size_t)(row + 8) * V_ + col) = r1;
        }
    }
}

extern "C" void kernel_launch(void* const* d_in, const int* in_sizes, int n_in,
                              void* d_out, int out_size) {
    const float* src  = (const float*)d_in[0];
    const int*   slen = (const int*)  d_in[1];
    const float* tgt  = (const float*)d_in[2];
    const int*   tlen = (const int*)  d_in[3];
    const float* W    = (const float*)d_in[4];
    const float* bias = (const float*)d_in[5];
    float* out = (float*)d_out;

    // fp16 conversions: W (524288), src (1048576), tgt (262144)
    {
        __half* w16; cudaGetSymbolAddress((void**)&w16, g_W16);
        __half* s16; cudaGetSymbolAddress((void**)&s16, g_S16);
        __half* t16; cudaGetSymbolAddress((void**)&t16, g_T16);
        convert_f2h_kernel<<<512, 256>>>(W, w16);
        convert_f2h_kernel<<<1024, 256>>>(src, s16);
        convert_f2h_kernel<<<256, 256>>>(tgt, t16);
    }

    cudaFuncSetAttribute(joiner_gemm_kernel,
                         cudaFuncAttributeMaxDynamicSharedMemorySize, SMEM_BYTES);
    dim3 grid(V_ / BN, (B_ * T_ * U_) / BM);   // (4, 1024)
    joiner_gemm_kernel<<<grid, 256, SMEM_BYTES>>>(bias, out);

    const long long N_OUT = (long long)B_ * T_ * U_ * V_;
    if ((long long)out_size >= N_OUT + 2 * B_) {
        write_lengths_kernel<<<1, 32>>>(slen, tlen, out + N_OUT);
    }
}

// round 17
// speedup vs baseline: 1.5363x; 1.5363x over previous
#include <cuda_runtime.h>
#include <cuda_fp16.h>
#include <cstdint>

// Problem constants
#define B_  8
#define T_  256
#define U_  64
#define D_  512
#define V_  1024

// Tiling: CTA 128x128, warp grid 2x4, warp tile 64x32, KC=64
#define BM 128
#define BN 128
#define KC 64             // k-chunk (4 x K=16 MMA steps)
#define NCHUNK 8          // D_/KC
#define ST 72             // smem row stride in halves (64 + 8 pad), conflict-free
#define A_TILE_H (BM * ST)   // 9216 halves per stage
#define B_TILE_H (BN * ST)   // 9216 halves per stage
#define SMEM_BYTES ((2 * A_TILE_H + 2 * B_TILE_H) * 2)   // 73728

// fp16 scratch (allocation-free per harness rules)
__device__ __align__(16) __half g_W16[V_ * D_];
__device__ __align__(16) __half g_S16[B_ * T_ * D_];
__device__ __align__(16) __half g_T16[B_ * U_ * D_];

__global__ void convert_f2h_kernel(const float* __restrict__ in, __half* __restrict__ out) {
    int i = (blockIdx.x * blockDim.x + threadIdx.x) * 4;
    float4 w = *(const float4*)(in + i);
    union { __half2 h[2]; uint2 u; } pack;
    pack.h[0] = __floats2half2_rn(w.x, w.y);
    pack.h[1] = __floats2half2_rn(w.z, w.w);
    *(uint2*)(out + i) = pack.u;
}

__global__ void write_lengths_kernel(const int* __restrict__ slen,
                                     const int* __restrict__ tlen,
                                     float* __restrict__ out_tail) {
    int i = threadIdx.x;
    if (i < B_)          out_tail[i] = (float)slen[i];
    else if (i < 2 * B_) out_tail[i] = (float)tlen[i - B_];
}

__device__ __forceinline__ void cp_async16(void* smem_dst, const void* gsrc) {
    uint32_t d = (uint32_t)__cvta_generic_to_shared(smem_dst);
    asm volatile("cp.async.ca.shared.global [%0], [%1], 16;" :: "r"(d), "l"(gsrc));
}
#define CP_COMMIT() asm volatile("cp.async.commit_group;" ::: "memory")
#define CP_WAIT0()  asm volatile("cp.async.wait_group 0;" ::: "memory")

// cp.async chunk c of B: 128 rows x 128B = 1024 x16B groups; 4 ops/thread.
__device__ __forceinline__ void cp_B(__half* Bs_s, int v0, int c, int tid) {
    #pragma unroll
    for (int it = 0; it < 4; ++it) {
        int G = tid + it * 256;       // 0..1023
        int n = G >> 3;               // B row 0..127
        int g = G & 7;                // 16B group within row
        cp_async16(Bs_s + n * ST + g * 8,
                   g_W16 + (size_t)(v0 + n) * D_ + c * KC + g * 8);
    }
}

// Load half h (32 cols) of chunk c's A operands (2 threads/row, 16 halves each).
__device__ __forceinline__ void load_A(int m_base, int c, int h, int tid,
                                       uint4 rs[2], uint4 rt[2]) {
    int r = tid >> 1;
    int col = c * KC + h * 32 + (tid & 1) * 16;
    int b = m_base >> 14;
    int t_idx = ((m_base & 16383) >> 6) + (r >> 6);
    const uint4* sp = (const uint4*)(g_S16 + (size_t)(b * T_ + t_idx) * D_ + col);
    const uint4* tp = (const uint4*)(g_T16 + (size_t)(b * U_ + (r & 63)) * D_ + col);
    rs[0] = sp[0]; rs[1] = sp[1];
    rt[0] = tp[0]; rt[1] = tp[1];
}

// relu(src+tgt) in half2, store 16 halves into half h of the stage.
__device__ __forceinline__ void store_A(__half* __restrict__ As_s, int h, int tid,
                                        const uint4 rs[2], const uint4 rt[2]) {
    int r = tid >> 1;
    __half* dst = As_s + r * ST + h * 32 + (tid & 1) * 16;
    const __half2 z = __float2half2_rn(0.f);
    #pragma unroll
    for (int j = 0; j < 2; ++j) {
        union { uint4 v; __half2 h2[4]; } a, b, o;
        a.v = rs[j]; b.v = rt[j];
        #pragma unroll
        for (int q = 0; q < 4; ++q) o.h2[q] = __hmax2(__hadd2(a.h2[q], b.h2[q]), z);
        *(uint4*)(dst + j * 8) = o.v;
    }
}

// Two k16 slabs (kk0, kk0+16) of MMAs against stage buffers.
__device__ __forceinline__ void compute_half(const __half* __restrict__ As_s,
                                             const __half* __restrict__ Bs_s,
                                             int kk0, int wm, int wn, int lane,
                                             float acc[4][4][4]) {
    #pragma unroll
    for (int kq = 0; kq < 2; ++kq) {
        const int kk = kk0 + kq * 16;
        uint32_t afr[4][4], bfr[2][4];
        #pragma unroll
        for (int mt = 0; mt < 4; ++mt) {
            int row = wm * 64 + mt * 16 + (lane & 15);
            int col = kk + ((lane >> 4) << 3);
            uint32_t addr = (uint32_t)__cvta_generic_to_shared(As_s + row * ST + col);
            asm volatile("ldmatrix.sync.aligned.m8n8.x4.shared.b16 {%0,%1,%2,%3}, [%4];"
                         : "=r"(afr[mt][0]), "=r"(afr[mt][1]), "=r"(afr[mt][2]), "=r"(afr[mt][3])
                         : "r"(addr));
        }
        #pragma unroll
        for (int nb = 0; nb < 2; ++nb) {
            int row = wn * 32 + nb * 16 + (lane & 15);
            int col = kk + ((lane >> 4) << 3);
            uint32_t addr = (uint32_t)__cvta_generic_to_shared(Bs_s + row * ST + col);
            asm volatile("ldmatrix.sync.aligned.m8n8.x4.shared.b16 {%0,%1,%2,%3}, [%4];"
                         : "=r"(bfr[nb][0]), "=r"(bfr[nb][1]), "=r"(bfr[nb][2]), "=r"(bfr[nb][3])
                         : "r"(addr));
        }
        #pragma unroll
        for (int mt = 0; mt < 4; ++mt)
            #pragma unroll
            for (int nt = 0; nt < 4; ++nt) {
                // n8 tile nt: regs {bfr[nt>>1][nt&1], bfr[nt>>1][(nt&1)+2]}
                asm volatile(
                    "mma.sync.aligned.m16n8k16.row.col.f32.f16.f16.f32 "
                    "{%0,%1,%2,%3}, {%4,%5,%6,%7}, {%8,%9}, {%0,%1,%2,%3};"
                    : "+f"(acc[mt][nt][0]), "+f"(acc[mt][nt][1]),
                      "+f"(acc[mt][nt][2]), "+f"(acc[mt][nt][3])
                    : "r"(afr[mt][0]), "r"(afr[mt][1]), "r"(afr[mt][2]), "r"(afr[mt][3]),
                      "r"(bfr[nt >> 1][nt & 1]), "r"(bfr[nt >> 1][(nt & 1) + 2]));
            }
    }
}

__global__ void __launch_bounds__(256, 2)
joiner_gemm_kernel(const float* __restrict__ bias, float* __restrict__ out)
{
    extern __shared__ __half sm[];
    __half* As = sm;                       // 2 stages x 9216
    __half* Bs = sm + 2 * A_TILE_H;        // 2 stages x 9216

    const int tid  = threadIdx.x;
    const int lane = tid & 31;
    const int warp = tid >> 5;
    const int wm = warp >> 2;     // 0..1
    const int wn = warp & 3;      // 0..3
    const int v0 = blockIdx.x * BN;
    const int m_base = blockIdx.y * BM;

    float acc[4][4][4];
    #pragma unroll
    for (int i = 0; i < 4; ++i)
        #pragma unroll
        for (int j = 0; j < 4; ++j)
            #pragma unroll
            for (int k = 0; k < 4; ++k) acc[i][j][k] = 0.f;

    // ---- prologue: chunk 0 (both halves) ----
    cp_B(Bs, v0, 0, tid);
    CP_COMMIT();
    {
        uint4 rs[2], rt[2];
        load_A(m_base, 0, 0, tid, rs, rt);
        store_A(As, 0, tid, rs, rt);
        load_A(m_base, 0, 1, tid, rs, rt);
        store_A(As, 1, tid, rs, rt);
    }
    CP_WAIT0();
    __syncthreads();

    // ---- main pipeline: one sync per KC=64 chunk ----
    for (int c = 0; c < NCHUNK; ++c) {
        const int s = c & 1;
        uint4 rs[2], rt[2];
        if (c < NCHUNK - 1) {
            cp_B(Bs + (s ^ 1) * B_TILE_H, v0, c + 1, tid);
            CP_COMMIT();
            load_A(m_base, c + 1, 0, tid, rs, rt);
        }
        compute_half(As + s * A_TILE_H, Bs + s * B_TILE_H, 0, wm, wn, lane, acc);
        if (c < NCHUNK - 1) {
            store_A(As + (s ^ 1) * A_TILE_H, 0, tid, rs, rt);
            load_A(m_base, c + 1, 1, tid, rs, rt);
        }
        compute_half(As + s * A_TILE_H, Bs + s * B_TILE_H, 32, wm, wn, lane, acc);
        if (c < NCHUNK - 1) {
            store_A(As + (s ^ 1) * A_TILE_H, 1, tid, rs, rt);
        }
        CP_WAIT0();
        __syncthreads();
    }

    // ---- epilogue: bias + fp32 store ----
    #pragma unroll
    for (int nt = 0; nt < 4; ++nt) {
        int col = v0 + wn * 32 + nt * 8 + ((lane & 3) << 1);
        float2 bv = *(const float2*)(bias + col);
        #pragma unroll
        for (int mt = 0; mt < 4; ++mt) {
            int row = m_base + wm * 64 + mt * 16 + (lane >> 2);
            float2 r0 = make_float2(acc[mt][nt][0] + bv.x, acc[mt][nt][1] + bv.y);
            float2 r1 = make_float2(acc[mt][nt][2] + bv.x, acc[mt][nt][3] + bv.y);
            *(float2*)(out + (size_t)row * V_ + col)       = r0;
            *(float2*)(out + (size_t)(row + 8) * V_ + col) = r1;
        }
    }
}

extern "C" void kernel_launch(void* const* d_in, const int* in_sizes, int n_in,
                              void* d_out, int out_size) {
    const float* src  = (const float*)d_in[0];
    const int*   slen = (const int*)  d_in[1];
    const float* tgt  = (const float*)d_in[2];
    const int*   tlen = (const int*)  d_in[3];
    const float* W    = (const float*)d_in[4];
    const float* bias = (const float*)d_in[5];
    float* out = (float*)d_out;

    // fp16 conversions: W (524288), src (1048576), tgt (262144)
    {
        __half* w16; cudaGetSymbolAddress((void**)&w16, g_W16);
        __half* s16; cudaGetSymbolAddress((void**)&s16, g_S16);
        __half* t16; cudaGetSymbolAddress((void**)&t16, g_T16);
        convert_f2h_kernel<<<512, 256>>>(W, w16);
        convert_f2h_kernel<<<1024, 256>>>(src, s16);
        convert_f2h_kernel<<<256, 256>>>(tgt, t16);
    }

    cudaFuncSetAttribute(joiner_gemm_kernel,
                         cudaFuncAttributeMaxDynamicSharedMemorySize, SMEM_BYTES);
    dim3 grid(V_ / BN, (B_ * T_ * U_) / BM);   // (8, 1024)
    joiner_gemm_kernel<<<grid, 256, SMEM_BYTES>>>(bias, out);

    const long long N_OUT = (long long)B_ * T_ * U_ * V_;
    if ((long long)out_size >= N_OUT + 2 * B_) {
        write_lengths_kernel<<<1, 32>>>(slen, tlen, out + N_OUT);
    }
}